// round 2
// baseline (speedup 1.0000x reference)
#include <cuda_runtime.h>
#include <cstdint>
#include <cstddef>

// Problem constants (fixed by the reference)
#define SEQ    2048
#define BATCH  32
#define XSIZE  256
#define HID    512
#define M_TOTAL (SEQ * BATCH)      // 65536 rows in the flattened GEMM
#define NB      (BATCH * HID)      // 16384 independent scan chains

// 128 MiB scratch for lin0 / y0 (allocation-free rule: device global)
__device__ float g_buf[(size_t)M_TOTAL * HID];

// ---------------------------------------------------------------------------
// SGEMM (NT): C[m][n] = sum_k A[m][k] * W[n][k]
// A: (M, K) row-major, W: (N, K) row-major, C: (M, HID) row-major (N == HID)
// Tiling: BM=BN=128, BK=16, TM=TN=8, 256 threads/block.
// ---------------------------------------------------------------------------
template <int BK>
__global__ __launch_bounds__(256)
void sgemm_nt(const float* __restrict__ A,
              const float* __restrict__ W,
              float* __restrict__ C,
              int K)
{
    __shared__ float As[BK][128];   // transposed: As[k][m]
    __shared__ float Bs[BK][128];   // transposed: Bs[k][n]

    const int tid = threadIdx.x;
    const int tx  = tid & 15;       // 16 thread-cols
    const int ty  = tid >> 4;       // 16 thread-rows

    const int mBlock = blockIdx.y * 128;
    const int nBlock = blockIdx.x * 128;

    const float* Aptr = A + (size_t)mBlock * K;
    const float* Wptr = W + (size_t)nBlock * K;

    float acc[8][8];
#pragma unroll
    for (int i = 0; i < 8; i++)
#pragma unroll
        for (int j = 0; j < 8; j++) acc[i][j] = 0.f;

    // Loader mapping: BK/4 float4 per tile row; 256 threads cover 128 rows in
    // (128 * BK/4) / 256 passes.
    const int f4PerRow  = BK / 4;                 // 4 for BK=16
    const int loadRow   = tid / f4PerRow;         // 0..63
    const int loadCol   = (tid % f4PerRow) * 4;   // 0,4,8,12
    const int rowStride = 256 / f4PerRow;         // 64

    for (int k0 = 0; k0 < K; k0 += BK) {
#pragma unroll
        for (int r = loadRow; r < 128; r += rowStride) {
            float4 v = *reinterpret_cast<const float4*>(
                Aptr + (size_t)r * K + k0 + loadCol);
            As[loadCol + 0][r] = v.x;
            As[loadCol + 1][r] = v.y;
            As[loadCol + 2][r] = v.z;
            As[loadCol + 3][r] = v.w;
        }
#pragma unroll
        for (int r = loadRow; r < 128; r += rowStride) {
            float4 v = *reinterpret_cast<const float4*>(
                Wptr + (size_t)r * K + k0 + loadCol);
            Bs[loadCol + 0][r] = v.x;
            Bs[loadCol + 1][r] = v.y;
            Bs[loadCol + 2][r] = v.z;
            Bs[loadCol + 3][r] = v.w;
        }
        __syncthreads();

#pragma unroll
        for (int kk = 0; kk < BK; kk++) {
            float am[8], bn[8];
#pragma unroll
            for (int i = 0; i < 8; i++) am[i] = As[kk][ty * 8 + i];
#pragma unroll
            for (int j = 0; j < 8; j++) bn[j] = Bs[kk][tx * 8 + j];
#pragma unroll
            for (int i = 0; i < 8; i++)
#pragma unroll
                for (int j = 0; j < 8; j++)
                    acc[i][j] = fmaf(am[i], bn[j], acc[i][j]);
        }
        __syncthreads();
    }

    // Epilogue: vectorized stores. C row stride is HID (total N).
    float* Cptr = C + (size_t)(mBlock + ty * 8) * HID + nBlock + tx * 8;
#pragma unroll
    for (int i = 0; i < 8; i++) {
#pragma unroll
        for (int j = 0; j < 8; j += 4) {
            float4 v = make_float4(acc[i][j], acc[i][j + 1],
                                   acc[i][j + 2], acc[i][j + 3]);
            *reinterpret_cast<float4*>(Cptr + (size_t)i * HID + j) = v;
        }
    }
}

// ---------------------------------------------------------------------------
// IndRNN scan: h_t = relu6(lin_t + b + rec * h_{t-1}), in-place on buf.
// One thread per (batch, hid) chain; group-of-8 prefetch to expose MLP while
// the dependent FMA/clamp chain executes.
// ---------------------------------------------------------------------------
__global__ __launch_bounds__(128)
void indrnn_scan(float* __restrict__ buf,
                 const float* __restrict__ bias,
                 const float* __restrict__ rec,
                 float* __restrict__ h_out)
{
    const int idx = blockIdx.x * blockDim.x + threadIdx.x;   // 0..NB-1
    const int hc  = idx & (HID - 1);
    const float r  = rec[hc];
    const float bb = bias[hc];

    float h = 0.f;
    float* p = buf + idx;

#pragma unroll 1
    for (int t = 0; t < SEQ; t += 8) {
        float v[8];
#pragma unroll
        for (int j = 0; j < 8; j++)
            v[j] = p[(size_t)(t + j) * NB];
#pragma unroll
        for (int j = 0; j < 8; j++) {
            h = fminf(fmaxf(fmaf(r, h, v[j] + bb), 0.f), 6.f);
            p[(size_t)(t + j) * NB] = h;
        }
    }
    h_out[idx] = h;
}

// ---------------------------------------------------------------------------
// Launch: GEMM0 -> scratch, scan0 in-place, GEMM1 -> d_out, scan1 in-place.
// Hiddens (2, BATCH, HID) live at the tail of d_out.
// ---------------------------------------------------------------------------
extern "C" void kernel_launch(void* const* d_in, const int* in_sizes, int n_in,
                              void* d_out, int out_size)
{
    const float* x    = (const float*)d_in[0];
    const float* W0   = (const float*)d_in[1];
    const float* b0   = (const float*)d_in[2];
    const float* rec0 = (const float*)d_in[3];
    const float* W1   = (const float*)d_in[4];
    const float* b1   = (const float*)d_in[5];
    const float* rec1 = (const float*)d_in[6];

    float* out = (float*)d_out;
    float* hid = out + ((size_t)out_size - (size_t)2 * BATCH * HID);

    // Resolve scratch address once (host API, capture-legal, allocation-free)
    static float* buf = nullptr;
    if (buf == nullptr)
        cudaGetSymbolAddress((void**)&buf, g_buf);

    dim3 grid(HID / 128, M_TOTAL / 128);         // (4, 512)

    // Layer 0
    sgemm_nt<16><<<grid, 256>>>(x, W0, buf, XSIZE);
    indrnn_scan<<<NB / 128, 128>>>(buf, b0, rec0, hid);          // h0 -> hid[0:NB]

    // Layer 1 (lin1 written straight into d_out, scanned in place)
    sgemm_nt<16><<<grid, 256>>>(buf, W1, out, HID);
    indrnn_scan<<<NB / 128, 128>>>(out, b1, rec1, hid + NB);     // h1 -> hid[NB:2NB]
}

// round 5
// speedup vs baseline: 2.3085x; 2.3085x over previous
#include <cuda_runtime.h>
#include <cuda_bf16.h>
#include <cstdint>
#include <cstddef>

// ---------------------------------------------------------------------------
// Problem constants
// ---------------------------------------------------------------------------
#define SEQ    2048
#define BATCH  32
#define XSIZE  256
#define HID    512
#define M_TOTAL (SEQ * BATCH)      // 65536
#define NB      (BATCH * HID)      // 16384 scan chains

// ---------------------------------------------------------------------------
// Scratch (allocation-free rule: device globals)
// ---------------------------------------------------------------------------
__device__ float         g_lin[(size_t)M_TOTAL * HID];    // 128 MiB (lin0)
__device__ __nv_bfloat16 g_xh [(size_t)M_TOTAL * XSIZE];
__device__ __nv_bfloat16 g_xl [(size_t)M_TOTAL * XSIZE];
__device__ __nv_bfloat16 g_yh [(size_t)M_TOTAL * HID];
__device__ __nv_bfloat16 g_yl [(size_t)M_TOTAL * HID];
__device__ __nv_bfloat16 g_w0h[HID * XSIZE], g_w0l[HID * XSIZE];
__device__ __nv_bfloat16 g_w1h[HID * HID],  g_w1l[HID * HID];

// ---------------------------------------------------------------------------
// PTX helpers (compute_100-safe: no tcgen05, no arch-suffixed features)
// ---------------------------------------------------------------------------
__device__ __forceinline__ uint32_t smem_u32(const void* p) {
    uint32_t a;
    asm("{ .reg .u64 t; cvta.to.shared.u64 t, %1; cvt.u32.u64 %0, t; }"
        : "=r"(a) : "l"(p));
    return a;
}

__device__ __forceinline__ void cp16(uint32_t dst, const void* src) {
    asm volatile("cp.async.cg.shared.global [%0], [%1], 16;"
                 :: "r"(dst), "l"(src) : "memory");
}

__device__ __forceinline__ void cp_commit() {
    asm volatile("cp.async.commit_group;" ::: "memory");
}

__device__ __forceinline__ void ldsm4(uint32_t* r, uint32_t addr) {
    asm volatile("ldmatrix.sync.aligned.m8n8.x4.shared.b16 {%0,%1,%2,%3}, [%4];"
        : "=r"(r[0]), "=r"(r[1]), "=r"(r[2]), "=r"(r[3]) : "r"(addr));
}

__device__ __forceinline__ void mma_bf16(float* c, const uint32_t* a, const uint32_t* b) {
    asm volatile(
        "mma.sync.aligned.m16n8k16.row.col.f32.bf16.bf16.f32 "
        "{%0,%1,%2,%3}, {%4,%5,%6,%7}, {%8,%9}, {%0,%1,%2,%3};"
        : "+f"(c[0]), "+f"(c[1]), "+f"(c[2]), "+f"(c[3])
        : "r"(a[0]), "r"(a[1]), "r"(a[2]), "r"(a[3]), "r"(b[0]), "r"(b[1]));
}

// ---------------------------------------------------------------------------
// Split-bf16 HMMA GEMM (NT): C[m][n] = sum_k A[m][k]*W[n][k],
// A = Ah+Al, W = Wh+Wl; 3 mma products per fragment pair (hh, hl, lh).
// BM=BN=128, BK=32, 256 threads, 8 warps (2 in M x 4 in N), warp tile 64x32.
// 2-stage cp.async double buffer. Smem rows padded to 40 halves (80B stride:
// 20 banks mod 32 -> ldmatrix phase conflict-free).
// ---------------------------------------------------------------------------
#define ROWH   40                      // halves per smem row (32 data + 8 pad)
#define TILEH  (128 * ROWH)            // 5120 halves per tile
#define STAGEH (4 * TILEH)             // Ah, Al, Wh, Wl
#define GEMM_SMEM (2 * STAGEH * 2)     // bytes (81920)

template <int K>
__device__ __forceinline__ void load_stage(
    uint32_t sb, int st,
    const __nv_bfloat16* pAh, const __nv_bfloat16* pAl,
    const __nv_bfloat16* pWh, const __nv_bfloat16* pWl,
    int k0, int tid)
{
    const __nv_bfloat16* srcs[4] = {pAh + k0, pAl + k0, pWh + k0, pWl + k0};
#pragma unroll
    for (int t = 0; t < 4; t++) {
        const __nv_bfloat16* src = srcs[t];
#pragma unroll
        for (int s = 0; s < 2; s++) {
            int idx = s * 256 + tid;         // 0..511
            int row = idx >> 2;
            int ch  = idx & 3;
            uint32_t d = sb + (uint32_t)(st * STAGEH + t * TILEH + row * ROWH + ch * 8) * 2;
            cp16(d, src + (size_t)row * K + ch * 8);
        }
    }
}

template <int K>
__global__ void __launch_bounds__(256)
gemm_mma(const __nv_bfloat16* __restrict__ Ah, const __nv_bfloat16* __restrict__ Al,
         const __nv_bfloat16* __restrict__ Wh, const __nv_bfloat16* __restrict__ Wl,
         float* __restrict__ C)
{
    extern __shared__ __nv_bfloat16 sm[];
    const uint32_t sb = smem_u32(sm);

    const int tid  = threadIdx.x;
    const int lane = tid & 31;
    const int wid  = tid >> 5;
    const int wm   = wid & 1;            // 0..1 (M)
    const int wn   = wid >> 1;           // 0..3 (N)

    const int mB = blockIdx.y * 128;
    const int nB = blockIdx.x * 128;

    const __nv_bfloat16* pAh = Ah + (size_t)mB * K;
    const __nv_bfloat16* pAl = Al + (size_t)mB * K;
    const __nv_bfloat16* pWh = Wh + (size_t)nB * K;
    const __nv_bfloat16* pWl = Wl + (size_t)nB * K;

    float acc[4][4][4];
#pragma unroll
    for (int i = 0; i < 4; i++)
#pragma unroll
        for (int j = 0; j < 4; j++)
#pragma unroll
            for (int r = 0; r < 4; r++) acc[i][j][r] = 0.f;

    const int L = K / 32;

    load_stage<K>(sb, 0, pAh, pAl, pWh, pWl, 0, tid);
    cp_commit();

    // ldmatrix lane addressing (constant across iterations)
    const int ar = wm * 64 + (lane & 15);            // A row within tile
    const int ach = (lane >> 4) << 3;                // A k-half offset
    const int br = wn * 32 + ((lane >> 4) << 3) + (lane & 7);  // B row
    const int bch = ((lane >> 3) & 1) << 3;                    // B k-half

    for (int it = 0; it < L; it++) {
        if (it + 1 < L) {
            load_stage<K>(sb, (it + 1) & 1, pAh, pAl, pWh, pWl, (it + 1) * 32, tid);
            cp_commit();
            asm volatile("cp.async.wait_group 1;" ::: "memory");
        } else {
            asm volatile("cp.async.wait_group 0;" ::: "memory");
        }
        __syncthreads();

        const uint32_t base = sb + (uint32_t)((it & 1) * STAGEH) * 2;

#pragma unroll
        for (int ks = 0; ks < 2; ks++) {
            uint32_t a_hi[4][4], a_lo[4][4], b_hi[2][4], b_lo[2][4];
            const int ac = ks * 16 + ach;
            const int bc = ks * 16 + bch;
#pragma unroll
            for (int mf = 0; mf < 4; mf++) {
                uint32_t ad = base + (uint32_t)((ar + mf * 16) * ROWH + ac) * 2;
                ldsm4(a_hi[mf], ad);
                ldsm4(a_lo[mf], ad + TILEH * 2);
            }
#pragma unroll
            for (int nf2 = 0; nf2 < 2; nf2++) {
                uint32_t bd = base + (uint32_t)(2 * TILEH) * 2
                            + (uint32_t)((br + nf2 * 16) * ROWH + bc) * 2;
                ldsm4(b_hi[nf2], bd);
                ldsm4(b_lo[nf2], bd + TILEH * 2);
            }
#pragma unroll
            for (int mf = 0; mf < 4; mf++) {
#pragma unroll
                for (int nf = 0; nf < 4; nf++) {
                    const uint32_t* bh = &b_hi[nf >> 1][(nf & 1) * 2];
                    const uint32_t* bl = &b_lo[nf >> 1][(nf & 1) * 2];
                    mma_bf16(acc[mf][nf], a_hi[mf], bh);
                    mma_bf16(acc[mf][nf], a_hi[mf], bl);
                    mma_bf16(acc[mf][nf], a_lo[mf], bh);
                }
            }
        }
        __syncthreads();
    }

    // Epilogue: c-frag layout -> global
    const int mbase = mB + wm * 64 + (lane >> 2);
    const int nbase = nB + wn * 32 + (lane & 3) * 2;
#pragma unroll
    for (int mf = 0; mf < 4; mf++) {
#pragma unroll
        for (int nf = 0; nf < 4; nf++) {
            const int m = mbase + mf * 16;
            const int n = nbase + nf * 8;
            *reinterpret_cast<float2*>(C + (size_t)m * HID + n) =
                make_float2(acc[mf][nf][0], acc[mf][nf][1]);
            *reinterpret_cast<float2*>(C + (size_t)(m + 8) * HID + n) =
                make_float2(acc[mf][nf][2], acc[mf][nf][3]);
        }
    }
}

// ---------------------------------------------------------------------------
// fp32 -> (bf16 hi, bf16 lo) split, vectorized
// ---------------------------------------------------------------------------
__global__ void __launch_bounds__(128)
split2(const float* __restrict__ a, __nv_bfloat16* __restrict__ hi,
       __nv_bfloat16* __restrict__ lo, int n)
{
    int i = (blockIdx.x * 128 + threadIdx.x) * 4;
    if (i >= n) return;
    float4 v = *reinterpret_cast<const float4*>(a + i);
    __nv_bfloat16 h0 = __float2bfloat16_rn(v.x);
    __nv_bfloat16 h1 = __float2bfloat16_rn(v.y);
    __nv_bfloat16 h2 = __float2bfloat16_rn(v.z);
    __nv_bfloat16 h3 = __float2bfloat16_rn(v.w);
    __nv_bfloat162 hA(h0, h1), hB(h2, h3);
    __nv_bfloat162 lA(__float2bfloat16_rn(v.x - __bfloat162float(h0)),
                      __float2bfloat16_rn(v.y - __bfloat162float(h1)));
    __nv_bfloat162 lB(__float2bfloat16_rn(v.z - __bfloat162float(h2)),
                      __float2bfloat16_rn(v.w - __bfloat162float(h3)));
    *reinterpret_cast<__nv_bfloat162*>(hi + i)     = hA;
    *reinterpret_cast<__nv_bfloat162*>(hi + i + 2) = hB;
    *reinterpret_cast<__nv_bfloat162*>(lo + i)     = lA;
    *reinterpret_cast<__nv_bfloat162*>(lo + i + 2) = lB;
}

// ---------------------------------------------------------------------------
// Scan layer 0: h = relu6(lin + b + rec*h); emit y0 as bf16 hi/lo split.
// Unroll 32 for MLP (R2 profile: latency-bound at unroll 8).
// ---------------------------------------------------------------------------
__global__ void __launch_bounds__(128)
scan_split(const float* __restrict__ lin, const float* __restrict__ bias,
           const float* __restrict__ rec,
           __nv_bfloat16* __restrict__ yh, __nv_bfloat16* __restrict__ yl,
           float* __restrict__ h_out)
{
    const int idx = blockIdx.x * blockDim.x + threadIdx.x;
    const int hc  = idx & (HID - 1);
    const float r  = rec[hc];
    const float bb = bias[hc];

    float h = 0.f;
    const float* p = lin + idx;

#pragma unroll 1
    for (int t = 0; t < SEQ; t += 32) {
        float v[32];
#pragma unroll
        for (int j = 0; j < 32; j++)
            v[j] = p[(size_t)(t + j) * NB];
#pragma unroll
        for (int j = 0; j < 32; j++) {
            h = fminf(fmaxf(fmaf(r, h, v[j] + bb), 0.f), 6.f);
            size_t off = (size_t)(t + j) * NB + idx;
            __nv_bfloat16 hh = __float2bfloat16_rn(h);
            yh[off] = hh;
            yl[off] = __float2bfloat16_rn(h - __bfloat162float(hh));
        }
    }
    h_out[idx] = h;
}

// ---------------------------------------------------------------------------
// Scan layer 1: in-place fp32, unroll 32
// ---------------------------------------------------------------------------
__global__ void __launch_bounds__(128)
scan_inplace(float* __restrict__ buf, const float* __restrict__ bias,
             const float* __restrict__ rec, float* __restrict__ h_out)
{
    const int idx = blockIdx.x * blockDim.x + threadIdx.x;
    const int hc  = idx & (HID - 1);
    const float r  = rec[hc];
    const float bb = bias[hc];

    float h = 0.f;
    float* p = buf + idx;

#pragma unroll 1
    for (int t = 0; t < SEQ; t += 32) {
        float v[32];
#pragma unroll
        for (int j = 0; j < 32; j++)
            v[j] = p[(size_t)(t + j) * NB];
#pragma unroll
        for (int j = 0; j < 32; j++) {
            h = fminf(fmaxf(fmaf(r, h, v[j] + bb), 0.f), 6.f);
            p[(size_t)(t + j) * NB] = h;
        }
    }
    h_out[idx] = h;
}

// ---------------------------------------------------------------------------
// Launch
// ---------------------------------------------------------------------------
extern "C" void kernel_launch(void* const* d_in, const int* in_sizes, int n_in,
                              void* d_out, int out_size)
{
    const float* x    = (const float*)d_in[0];
    const float* W0   = (const float*)d_in[1];
    const float* b0   = (const float*)d_in[2];
    const float* rec0 = (const float*)d_in[3];
    const float* W1   = (const float*)d_in[4];
    const float* b1   = (const float*)d_in[5];
    const float* rec1 = (const float*)d_in[6];

    float* out = (float*)d_out;
    float* hid = out + ((size_t)out_size - (size_t)2 * BATCH * HID);

    static float* lin = nullptr;
    static __nv_bfloat16 *xh, *xl, *yh, *yl, *w0h, *w0l, *w1h, *w1l;
    static bool init = false;
    if (!init) {
        cudaGetSymbolAddress((void**)&lin, g_lin);
        cudaGetSymbolAddress((void**)&xh,  g_xh);
        cudaGetSymbolAddress((void**)&xl,  g_xl);
        cudaGetSymbolAddress((void**)&yh,  g_yh);
        cudaGetSymbolAddress((void**)&yl,  g_yl);
        cudaGetSymbolAddress((void**)&w0h, g_w0h);
        cudaGetSymbolAddress((void**)&w0l, g_w0l);
        cudaGetSymbolAddress((void**)&w1h, g_w1h);
        cudaGetSymbolAddress((void**)&w1l, g_w1l);
        cudaFuncSetAttribute(gemm_mma<XSIZE>,
            cudaFuncAttributeMaxDynamicSharedMemorySize, GEMM_SMEM);
        cudaFuncSetAttribute(gemm_mma<HID>,
            cudaFuncAttributeMaxDynamicSharedMemorySize, GEMM_SMEM);
        init = true;
    }

    // Split inputs to bf16 hi/lo
    split2<<<(M_TOTAL * XSIZE) / 512, 128>>>(x,  xh,  xl,  M_TOTAL * XSIZE);
    split2<<<(HID * XSIZE) / 512, 128>>>(W0, w0h, w0l, HID * XSIZE);
    split2<<<(HID * HID)  / 512, 128>>>(W1, w1h, w1l, HID * HID);

    dim3 grid(HID / 128, M_TOTAL / 128);   // (4, 512)

    // Layer 0
    gemm_mma<XSIZE><<<grid, 256, GEMM_SMEM>>>(xh, xl, w0h, w0l, lin);
    scan_split<<<NB / 128, 128>>>(lin, b0, rec0, yh, yl, hid);

    // Layer 1 (lin1 straight into d_out, scanned in place)
    gemm_mma<HID><<<grid, 256, GEMM_SMEM>>>(yh, yl, w1h, w1l, out);
    scan_inplace<<<NB / 128, 128>>>(out, b1, rec1, hid + NB);
}